// round 1
// baseline (speedup 1.0000x reference)
#include <cuda_runtime.h>
#include <math.h>
#include <float.h>
#include <stdint.h>

#define N_NODES 50000
#define N_EDGES 1600000
#define E_TOT   1650000      // edges + self loops
#define IN_CH   128
#define HC      128          // HEADS * OUT_CH
#define HEADS   4
#define NHC     (N_NODES * HC)   // 6,400,000
#define NEG_SLOPE 0.2f

// ---------------- device scratch (static: no allocations allowed) ----------------
__device__ float g_h[(size_t)N_NODES * HC];        // projected features [N,128]
__device__ float g_asrc[N_NODES * HEADS];          // per-node src attention term
__device__ float g_adst[N_NODES * HEADS];          // per-node dst attention term
__device__ float g_amax[N_NODES * HEADS];          // segment max per (dst, head)
__device__ float g_den [N_NODES * HEADS];          // segment expsum per (dst, head)
__device__ int   g_cnt[N_NODES];                   // in-degree counts
__device__ int   g_cur[N_NODES];                   // placement cursors
__device__ int   g_rowstart[N_NODES + 1];          // CSR row offsets (by dst)
__device__ int   g_srcp[E_TOT];                    // src node id, grouped by dst

// ---------------- K1: h = x @ W  (fp32, W resident in smem) ----------------
// block: 256 threads = 16x16; tile: 64 rows x 128 cols; each thread 4x8 outputs.
__global__ void k_gemm(const float* __restrict__ x, const float* __restrict__ W) {
    extern __shared__ float sm[];
    float* ws = sm;                 // [128][132] padded
    float* xs = sm + 128 * 132;     // [64][132]  padded

    const int tid = threadIdx.x;
    const int m0  = blockIdx.x * 64;

    // load W (128x128) into smem, padded pitch 132
    const float4* W4 = (const float4*)W;
    for (int i = tid; i < 128 * 32; i += 256) {
        int k = i >> 5, c4 = i & 31;
        float4 w = W4[i];
        float* p = ws + k * 132 + c4 * 4;
        p[0] = w.x; p[1] = w.y; p[2] = w.z; p[3] = w.w;
    }
    // load x tile (64x128)
    const float4* x4 = (const float4*)x;
    for (int i = tid; i < 64 * 32; i += 256) {
        int r = i >> 5, c4 = i & 31;
        int gr = m0 + r;
        float4 v = make_float4(0.f, 0.f, 0.f, 0.f);
        if (gr < N_NODES) v = x4[(size_t)gr * 32 + c4];
        float* p = xs + r * 132 + c4 * 4;
        p[0] = v.x; p[1] = v.y; p[2] = v.z; p[3] = v.w;
    }
    __syncthreads();

    const int tx = tid & 15, ty = tid >> 4;
    float acc[4][8];
#pragma unroll
    for (int i = 0; i < 4; i++)
#pragma unroll
        for (int j = 0; j < 8; j++) acc[i][j] = 0.f;

#pragma unroll 4
    for (int k = 0; k < 128; k++) {
        float xv[4];
#pragma unroll
        for (int i = 0; i < 4; i++) xv[i] = xs[(ty * 4 + i) * 132 + k];
        const float* wp = ws + k * 132 + tx * 8;
        float wv[8];
#pragma unroll
        for (int j = 0; j < 8; j++) wv[j] = wp[j];
#pragma unroll
        for (int i = 0; i < 4; i++)
#pragma unroll
            for (int j = 0; j < 8; j++) acc[i][j] = fmaf(xv[i], wv[j], acc[i][j]);
    }

#pragma unroll
    for (int i = 0; i < 4; i++) {
        int r = m0 + ty * 4 + i;
        if (r < N_NODES) {
            float* o = g_h + (size_t)r * 128 + tx * 8;
            float4 a = make_float4(acc[i][0], acc[i][1], acc[i][2], acc[i][3]);
            float4 b = make_float4(acc[i][4], acc[i][5], acc[i][6], acc[i][7]);
            *(float4*)(o)     = a;
            *(float4*)(o + 4) = b;
        }
    }
}

// ---------------- K2: per-node attention terms ----------------
__global__ void k_att(const float* __restrict__ att_src, const float* __restrict__ att_dst) {
    int t = blockIdx.x * blockDim.x + threadIdx.x;
    if (t >= N_NODES * HEADS) return;
    int n = t >> 2, hd = t & 3;
    const float4* hp = (const float4*)(g_h + (size_t)n * 128 + hd * 32);
    const float4* a4 = (const float4*)att_src + hd * 8;
    const float4* b4 = (const float4*)att_dst + hd * 8;
    float s = 0.f, d = 0.f;
#pragma unroll
    for (int j = 0; j < 8; j++) {
        float4 v = hp[j];
        float4 a = __ldg(&a4[j]);
        float4 b = __ldg(&b4[j]);
        s += v.x * a.x + v.y * a.y + v.z * a.z + v.w * a.w;
        d += v.x * b.x + v.y * b.y + v.z * b.z + v.w * b.w;
    }
    g_asrc[t] = s;
    g_adst[t] = d;
}

// ---------------- CSR build ----------------
__global__ void k_zero_cnt() {
    int t = blockIdx.x * blockDim.x + threadIdx.x;
    if (t < N_NODES) g_cnt[t] = 0;
}

__global__ void k_count(const int* __restrict__ dst) {
    int e = blockIdx.x * blockDim.x + threadIdx.x;
    if (e >= E_TOT) return;
    int d = (e < N_EDGES) ? dst[e] : (e - N_EDGES);
    atomicAdd(&g_cnt[d], 1);
}

#define SCAN_T 1024
#define SCAN_CH ((N_NODES + SCAN_T - 1) / SCAN_T)   // 49
__global__ void k_scan() {
    __shared__ int ssum[SCAN_T];
    int t = threadIdx.x;
    int lo = t * SCAN_CH;
    int hi = lo + SCAN_CH; if (hi > N_NODES) hi = N_NODES;
    int s = 0;
    for (int i = lo; i < hi; i++) s += g_cnt[i];
    ssum[t] = s;
    __syncthreads();
    for (int off = 1; off < SCAN_T; off <<= 1) {
        int v = 0;
        if (t >= off) v = ssum[t - off];
        __syncthreads();
        ssum[t] += v;
        __syncthreads();
    }
    int run = (t == 0) ? 0 : ssum[t - 1];
    for (int i = lo; i < hi; i++) {
        int c = g_cnt[i];
        g_rowstart[i] = run;
        g_cur[i] = run;
        run += c;
    }
    if (t == SCAN_T - 1) g_rowstart[N_NODES] = run;  // == E_TOT
}

__global__ void k_place(const int* __restrict__ src, const int* __restrict__ dst) {
    int e = blockIdx.x * blockDim.x + threadIdx.x;
    if (e >= E_TOT) return;
    int d, s;
    if (e < N_EDGES) { s = src[e]; d = dst[e]; }
    else             { s = e - N_EDGES; d = s; }
    int pos = atomicAdd(&g_cur[d], 1);
    g_srcp[pos] = s;
}

// ---------------- K3: softmax + weighted aggregate, one warp per dst node ----------------
__global__ void k_agg(const float* __restrict__ bias, float* __restrict__ out) {
    int gt = blockIdx.x * blockDim.x + threadIdx.x;
    int warp = gt >> 5, lane = gt & 31;
    int nw = (gridDim.x * blockDim.x) >> 5;
    int hd = lane >> 3;  // head for this lane (lane covers channels lane*4 .. lane*4+3)

    for (int n = warp; n < N_NODES; n += nw) {
        int beg = g_rowstart[n];
        int end = g_rowstart[n + 1];
        float ad = g_adst[n * 4 + hd];

        // pass 1: segment max (per head; identical across the 8 lanes of a head)
        float mx = -FLT_MAX;
        for (int p = beg; p < end; p++) {
            int s = g_srcp[p];
            float lg = g_asrc[s * 4 + hd] + ad;
            lg = lg > 0.f ? lg : NEG_SLOPE * lg;
            mx = fmaxf(mx, lg);
        }

        // pass 2: exp-sum + weighted accumulate of h[src]
        float den = 0.f;
        float4 acc = make_float4(0.f, 0.f, 0.f, 0.f);
        for (int p = beg; p < end; p++) {
            int s = g_srcp[p];
            float lg = g_asrc[s * 4 + hd] + ad;
            lg = lg > 0.f ? lg : NEG_SLOPE * lg;
            float ex = expf(lg - mx);
            den += ex;
            float4 hv = *(const float4*)(g_h + (size_t)s * 128 + lane * 4);
            acc.x = fmaf(ex, hv.x, acc.x);
            acc.y = fmaf(ex, hv.y, acc.y);
            acc.z = fmaf(ex, hv.z, acc.z);
            acc.w = fmaf(ex, hv.w, acc.w);
        }

        float inv = 1.f / (den + 1e-16f);
        float4 b = *(const float4*)(bias + lane * 4);
        float4 o;
        o.x = fmaf(acc.x, inv, b.x);
        o.y = fmaf(acc.y, inv, b.y);
        o.z = fmaf(acc.z, inv, b.z);
        o.w = fmaf(acc.w, inv, b.w);
        *(float4*)(out + (size_t)n * 128 + lane * 4) = o;

        // stash per-(node,head) max & denom for the alpha output kernel
        float m0 = __shfl_sync(0xffffffffu, mx, 0);
        float m1 = __shfl_sync(0xffffffffu, mx, 8);
        float m2 = __shfl_sync(0xffffffffu, mx, 16);
        float m3 = __shfl_sync(0xffffffffu, mx, 24);
        float d0 = __shfl_sync(0xffffffffu, den, 0);
        float d1 = __shfl_sync(0xffffffffu, den, 8);
        float d2 = __shfl_sync(0xffffffffu, den, 16);
        float d3 = __shfl_sync(0xffffffffu, den, 24);
        if (lane == 0) {
            *(float4*)(g_amax + n * 4) = make_float4(m0, m1, m2, m3);
            *(float4*)(g_den  + n * 4) = make_float4(d0, d1, d2, d3);
        }
    }
}

// ---------------- K4: normalized alpha output ----------------
__global__ void k_alpha(const int* __restrict__ src, const int* __restrict__ dst,
                        float* __restrict__ alpha_out) {
    int e = blockIdx.x * blockDim.x + threadIdx.x;
    if (e >= E_TOT) return;
    int s, d;
    if (e < N_EDGES) { s = src[e]; d = dst[e]; }
    else             { s = e - N_EDGES; d = s; }
    float4 as  = *(const float4*)(g_asrc + (size_t)s * 4);
    float4 adv = *(const float4*)(g_adst + (size_t)d * 4);
    float4 mxv = *(const float4*)(g_amax + (size_t)d * 4);
    float4 dnv = *(const float4*)(g_den  + (size_t)d * 4);
    float4 r;
    {
        float lg = as.x + adv.x; lg = lg > 0.f ? lg : NEG_SLOPE * lg;
        r.x = expf(lg - mxv.x) / (dnv.x + 1e-16f);
    }
    {
        float lg = as.y + adv.y; lg = lg > 0.f ? lg : NEG_SLOPE * lg;
        r.y = expf(lg - mxv.y) / (dnv.y + 1e-16f);
    }
    {
        float lg = as.z + adv.z; lg = lg > 0.f ? lg : NEG_SLOPE * lg;
        r.z = expf(lg - mxv.z) / (dnv.z + 1e-16f);
    }
    {
        float lg = as.w + adv.w; lg = lg > 0.f ? lg : NEG_SLOPE * lg;
        r.w = expf(lg - mxv.w) / (dnv.w + 1e-16f);
    }
    *(float4*)(alpha_out + (size_t)e * 4) = r;
}

// ---------------- launch ----------------
extern "C" void kernel_launch(void* const* d_in, const int* in_sizes, int n_in,
                              void* d_out, int out_size) {
    const float* x       = (const float*)d_in[0];
    const int*   ei      = (const int*)d_in[1];   // [2, E] int32 (JAX default x64-off)
    const float* W       = (const float*)d_in[2];
    const float* att_src = (const float*)d_in[3];
    const float* att_dst = (const float*)d_in[4];
    const float* bias    = (const float*)d_in[5];
    float* out = (float*)d_out;

    const int* src = ei;
    const int* dst = ei + N_EDGES;

    const bool has_alpha = (out_size >= NHC + E_TOT * HEADS);

    const int GEMM_SMEM = (128 + 64) * 132 * 4;  // 101376 bytes
    cudaFuncSetAttribute(k_gemm, cudaFuncAttributeMaxDynamicSharedMemorySize, GEMM_SMEM);

    // projection + attention terms
    k_gemm<<<(N_NODES + 63) / 64, 256, GEMM_SMEM>>>(x, W);
    k_att<<<(N_NODES * HEADS + 255) / 256, 256>>>(att_src, att_dst);

    // CSR by dst (rebuilt every launch; deterministic work)
    k_zero_cnt<<<(N_NODES + 255) / 256, 256>>>();
    k_count<<<(E_TOT + 255) / 256, 256>>>(dst);
    k_scan<<<1, SCAN_T>>>();
    k_place<<<(E_TOT + 255) / 256, 256>>>(src, dst);

    // softmax + aggregate: one warp per node => 50000 warps
    k_agg<<<6250, 256>>>(bias, out);

    if (has_alpha) {
        k_alpha<<<(E_TOT + 255) / 256, 256>>>(src, dst, out + NHC);
    }
}

// round 2
// speedup vs baseline: 1.0805x; 1.0805x over previous
#include <cuda_runtime.h>
#include <cuda_fp16.h>
#include <math.h>
#include <float.h>
#include <stdint.h>

#define N_NODES 50000
#define N_EDGES 1600000
#define E_TOT   1650000      // edges + self loops
#define IN_CH   128
#define HC      128          // HEADS * OUT_CH
#define HEADS   4
#define NHC     (N_NODES * HC)   // 6,400,000
#define NEG_SLOPE 0.2f

// ---------------- device scratch (static: no allocations allowed) ----------------
__device__ __align__(16) __half g_hh[(size_t)NHC];   // projected features fp16 [N,128]
__device__ __align__(16) float g_asrc[N_NODES * HEADS];
__device__ __align__(16) float g_adst[N_NODES * HEADS];
__device__ int   g_cnt[N_NODES];
__device__ int   g_cur[N_NODES];
__device__ int   g_rowstart[N_NODES + 1];
__device__ __align__(16) int2 g_sed[E_TOT];          // {src, edge_id} grouped by dst

// ---------------- K1: h = x @ W (fp32) + fused att dots, fp16 h output ----------------
// block: 256 threads = 16x16; tile: 64 rows x 128 cols; each thread 4x8 outputs.
__global__ __launch_bounds__(256) void k_gemm(const float* __restrict__ x,
                                              const float* __restrict__ W,
                                              const float* __restrict__ att_src,
                                              const float* __restrict__ att_dst) {
    extern __shared__ float sm[];
    float* ws = sm;                 // [128][132]
    float* xs = sm + 128 * 132;     // [64][132]

    const int tid = threadIdx.x;
    const int m0  = blockIdx.x * 64;

    const float4* W4 = (const float4*)W;
    for (int i = tid; i < 128 * 32; i += 256) {
        int k = i >> 5, c4 = i & 31;
        float4 w = W4[i];
        float* p = ws + k * 132 + c4 * 4;
        p[0] = w.x; p[1] = w.y; p[2] = w.z; p[3] = w.w;
    }
    const float4* x4 = (const float4*)x;
    for (int i = tid; i < 64 * 32; i += 256) {
        int r = i >> 5, c4 = i & 31;
        int gr = m0 + r;
        float4 v = make_float4(0.f, 0.f, 0.f, 0.f);
        if (gr < N_NODES) v = x4[(size_t)gr * 32 + c4];
        float* p = xs + r * 132 + c4 * 4;
        p[0] = v.x; p[1] = v.y; p[2] = v.z; p[3] = v.w;
    }
    __syncthreads();

    const int tx = tid & 15, ty = tid >> 4;
    float acc[4][8];
#pragma unroll
    for (int i = 0; i < 4; i++)
#pragma unroll
        for (int j = 0; j < 8; j++) acc[i][j] = 0.f;

#pragma unroll 4
    for (int k = 0; k < 128; k++) {
        float xv[4];
#pragma unroll
        for (int i = 0; i < 4; i++) xv[i] = xs[(ty * 4 + i) * 132 + k];
        const float* wp = ws + k * 132 + tx * 8;
        float wv[8];
#pragma unroll
        for (int j = 0; j < 8; j++) wv[j] = wp[j];
#pragma unroll
        for (int i = 0; i < 4; i++)
#pragma unroll
            for (int j = 0; j < 8; j++) acc[i][j] = fmaf(xv[i], wv[j], acc[i][j]);
    }

    // --- fused attention dots: head g = tx>>2, in-head col base = (tx&3)*8 ---
    const int g  = tx >> 2;
    const int cb = g * 32 + (tx & 3) * 8;
    float As[8], Ad[8];
    {
        float4 a0 = __ldg((const float4*)(att_src + cb));
        float4 a1 = __ldg((const float4*)(att_src + cb + 4));
        float4 b0 = __ldg((const float4*)(att_dst + cb));
        float4 b1 = __ldg((const float4*)(att_dst + cb + 4));
        As[0]=a0.x;As[1]=a0.y;As[2]=a0.z;As[3]=a0.w;As[4]=a1.x;As[5]=a1.y;As[6]=a1.z;As[7]=a1.w;
        Ad[0]=b0.x;Ad[1]=b0.y;Ad[2]=b0.z;Ad[3]=b0.w;Ad[4]=b1.x;Ad[5]=b1.y;Ad[6]=b1.z;Ad[7]=b1.w;
    }
    float pa[4], pb[4];
#pragma unroll
    for (int i = 0; i < 4; i++) {
        float s = 0.f, d = 0.f;
#pragma unroll
        for (int j = 0; j < 8; j++) { s = fmaf(acc[i][j], As[j], s); d = fmaf(acc[i][j], Ad[j], d); }
        pa[i] = s; pb[i] = d;
    }
#pragma unroll
    for (int off = 1; off <= 2; off <<= 1) {
#pragma unroll
        for (int i = 0; i < 4; i++) {
            pa[i] += __shfl_xor_sync(0xffffffffu, pa[i], off);
            pb[i] += __shfl_xor_sync(0xffffffffu, pb[i], off);
        }
    }

#pragma unroll
    for (int i = 0; i < 4; i++) {
        int r = m0 + ty * 4 + i;
        if (r < N_NODES) {
            // fp16 h
            __half2 hp[4];
            hp[0] = __floats2half2_rn(acc[i][0], acc[i][1]);
            hp[1] = __floats2half2_rn(acc[i][2], acc[i][3]);
            hp[2] = __floats2half2_rn(acc[i][4], acc[i][5]);
            hp[3] = __floats2half2_rn(acc[i][6], acc[i][7]);
            *(uint4*)(g_hh + (size_t)r * 128 + tx * 8) = *(uint4*)hp;
            if ((tx & 3) == 0) {
                g_asrc[r * 4 + g] = pa[i];
                g_adst[r * 4 + g] = pb[i];
            }
        }
    }
}

// ---------------- CSR build ----------------
__global__ void k_zero_cnt() {
    int t = blockIdx.x * blockDim.x + threadIdx.x;
    if (t < N_NODES) g_cnt[t] = 0;
}

__global__ void k_count(const int* __restrict__ dst) {
    int t = blockIdx.x * blockDim.x + threadIdx.x;
    if (t >= N_EDGES / 4) return;
    int4 d = ((const int4*)dst)[t];
    atomicAdd(&g_cnt[d.x], 1);
    atomicAdd(&g_cnt[d.y], 1);
    atomicAdd(&g_cnt[d.z], 1);
    atomicAdd(&g_cnt[d.w], 1);
}

#define SCAN_T 1024
#define SCAN_CH ((N_NODES + SCAN_T - 1) / SCAN_T)   // 49
__global__ void k_scan() {
    __shared__ int ssum[SCAN_T];
    int t = threadIdx.x;
    int lo = t * SCAN_CH;
    int hi = lo + SCAN_CH; if (hi > N_NODES) hi = N_NODES;
    int s = 0;
    for (int i = lo; i < hi; i++) s += g_cnt[i] + 1;   // +1: self loop
    ssum[t] = s;
    __syncthreads();
    for (int off = 1; off < SCAN_T; off <<= 1) {
        int v = 0;
        if (t >= off) v = ssum[t - off];
        __syncthreads();
        ssum[t] += v;
        __syncthreads();
    }
    int run = (t == 0) ? 0 : ssum[t - 1];
    for (int i = lo; i < hi; i++) {
        int c = g_cnt[i] + 1;
        g_rowstart[i] = run;
        g_cur[i] = run;
        run += c;
    }
    if (t == SCAN_T - 1) g_rowstart[N_NODES] = run;  // == E_TOT
}

__global__ void k_place(const int* __restrict__ src, const int* __restrict__ dst) {
    int e = blockIdx.x * blockDim.x + threadIdx.x;
    if (e >= E_TOT) return;
    int d, s;
    if (e < N_EDGES) { s = src[e]; d = dst[e]; }
    else             { s = e - N_EDGES; d = s; }
    int pos = atomicAdd(&g_cur[d], 1);
    g_sed[pos] = make_int2(s, e);
}

// ---------------- K3: softmax (no max-shift) + aggregate + alpha, one warp per node ----
__global__ __launch_bounds__(256) void k_agg(const float* __restrict__ bias,
                                             float* __restrict__ out,
                                             float* __restrict__ alpha_out) {
    int gt = blockIdx.x * blockDim.x + threadIdx.x;
    int warp = gt >> 5, lane = gt & 31;
    int nw = (gridDim.x * blockDim.x) >> 5;
    int hd = lane >> 3;   // head for this lane; lane covers channels lane*4..lane*4+3

    float4 b = *(const float4*)(bias + lane * 4);

    for (int n = warp; n < N_NODES; n += nw) {
        int beg = g_rowstart[n];
        int end = g_rowstart[n + 1];
        float ad = g_adst[n * 4 + hd];

        float den = 0.f;
        float4 acc = make_float4(0.f, 0.f, 0.f, 0.f);
        for (int p = beg; p < end; p++) {
            int2 se = g_sed[p];
            float lg = g_asrc[se.x * 4 + hd] + ad;
            lg = lg > 0.f ? lg : NEG_SLOPE * lg;
            float ex = __expf(lg);           // logits bounded ~|10|: no overflow, shift-free
            den += ex;
            uint2 hv = *(const uint2*)(g_hh + (size_t)se.x * 128 + lane * 4);
            float2 f0 = __half22float2(*(__half2*)&hv.x);
            float2 f1 = __half22float2(*(__half2*)&hv.y);
            acc.x = fmaf(ex, f0.x, acc.x);
            acc.y = fmaf(ex, f0.y, acc.y);
            acc.z = fmaf(ex, f1.x, acc.z);
            acc.w = fmaf(ex, f1.y, acc.w);
            if (alpha_out && (lane & 7) == 0)
                alpha_out[(size_t)se.y * 4 + hd] = ex;   // unnormalized; scaled below
        }

        float inv = 1.f / (den + 1e-16f);
        float4 o;
        o.x = fmaf(acc.x, inv, b.x);
        o.y = fmaf(acc.y, inv, b.y);
        o.z = fmaf(acc.z, inv, b.z);
        o.w = fmaf(acc.w, inv, b.w);
        *(float4*)(out + (size_t)n * 128 + lane * 4) = o;

        if (alpha_out) {
            float i0 = __shfl_sync(0xffffffffu, inv, 0);
            float i1 = __shfl_sync(0xffffffffu, inv, 8);
            float i2 = __shfl_sync(0xffffffffu, inv, 16);
            float i3 = __shfl_sync(0xffffffffu, inv, 24);
            __syncwarp();   // make lanes' ex stores visible to all lanes
            for (int p = beg + lane; p < end; p += 32) {
                int e = g_sed[p].y;
                float4 v = *(float4*)(alpha_out + (size_t)e * 4);
                v.x *= i0; v.y *= i1; v.z *= i2; v.w *= i3;
                *(float4*)(alpha_out + (size_t)e * 4) = v;
            }
        }
    }
}

// ---------------- launch ----------------
extern "C" void kernel_launch(void* const* d_in, const int* in_sizes, int n_in,
                              void* d_out, int out_size) {
    const float* x       = (const float*)d_in[0];
    const int*   ei      = (const int*)d_in[1];   // [2, E] int32
    const float* W       = (const float*)d_in[2];
    const float* att_src = (const float*)d_in[3];
    const float* att_dst = (const float*)d_in[4];
    const float* bias    = (const float*)d_in[5];
    float* out = (float*)d_out;

    const int* src = ei;
    const int* dst = ei + N_EDGES;

    float* alpha_out = (out_size >= NHC + E_TOT * HEADS) ? (out + NHC) : nullptr;

    const int GEMM_SMEM = (128 + 64) * 132 * 4;  // 101376 bytes
    cudaFuncSetAttribute(k_gemm, cudaFuncAttributeMaxDynamicSharedMemorySize, GEMM_SMEM);

    k_gemm<<<(N_NODES + 63) / 64, 256, GEMM_SMEM>>>(x, W, att_src, att_dst);

    k_zero_cnt<<<(N_NODES + 255) / 256, 256>>>();
    k_count<<<(N_EDGES / 4 + 255) / 256, 256>>>(dst);
    k_scan<<<1, SCAN_T>>>();
    k_place<<<(E_TOT + 255) / 256, 256>>>(src, dst);

    k_agg<<<6250, 256>>>(bias, out, alpha_out);
}

// round 3
// speedup vs baseline: 1.3977x; 1.2936x over previous
#include <cuda_runtime.h>
#include <cuda_fp16.h>
#include <math.h>
#include <float.h>
#include <stdint.h>

#define N_NODES 50000
#define N_EDGES 1600000
#define E_TOT   1650000      // edges + self loops
#define IN_CH   128
#define HC      128          // HEADS * OUT_CH
#define HEADS   4
#define NHC     (N_NODES * HC)   // 6,400,000
#define NEG_SLOPE 0.2f

#define SB 1024
#define NB ((N_NODES + SB - 1) / SB)   // 49 scan blocks

// ---------------- device scratch (static: no allocations allowed) ----------------
__device__ __align__(16) __half g_hh[(size_t)NHC];   // projected features fp16 [N,128]
__device__ __align__(16) float g_asrc[N_NODES * HEADS];
__device__ __align__(16) float g_adst[N_NODES * HEADS];
__device__ int   g_cnt[N_NODES];
__device__ int   g_cur[N_NODES];
__device__ int   g_rowstart[N_NODES + 1];
__device__ int   g_bsum[NB];
__device__ int   g_boff[NB];
__device__ __align__(16) int2 g_sed[E_TOT];          // {src, edge_id} grouped by dst

// ---------------- K1: h = x @ W (fp32) + fused att dots, fp16 h output ----------------
__global__ __launch_bounds__(256) void k_gemm(const float* __restrict__ x,
                                              const float* __restrict__ W,
                                              const float* __restrict__ att_src,
                                              const float* __restrict__ att_dst) {
    extern __shared__ float sm[];
    float* ws = sm;                 // [128][132]
    float* xs = sm + 128 * 132;     // [64][132]

    const int tid = threadIdx.x;
    const int m0  = blockIdx.x * 64;

    const float4* W4 = (const float4*)W;
    for (int i = tid; i < 128 * 32; i += 256) {
        int k = i >> 5, c4 = i & 31;
        float4 w = W4[i];
        float* p = ws + k * 132 + c4 * 4;
        p[0] = w.x; p[1] = w.y; p[2] = w.z; p[3] = w.w;
    }
    const float4* x4 = (const float4*)x;
    for (int i = tid; i < 64 * 32; i += 256) {
        int r = i >> 5, c4 = i & 31;
        int gr = m0 + r;
        float4 v = make_float4(0.f, 0.f, 0.f, 0.f);
        if (gr < N_NODES) v = x4[(size_t)gr * 32 + c4];
        float* p = xs + r * 132 + c4 * 4;
        p[0] = v.x; p[1] = v.y; p[2] = v.z; p[3] = v.w;
    }
    __syncthreads();

    const int tx = tid & 15, ty = tid >> 4;
    float acc[4][8];
#pragma unroll
    for (int i = 0; i < 4; i++)
#pragma unroll
        for (int j = 0; j < 8; j++) acc[i][j] = 0.f;

#pragma unroll 4
    for (int k = 0; k < 128; k++) {
        float xv[4];
#pragma unroll
        for (int i = 0; i < 4; i++) xv[i] = xs[(ty * 4 + i) * 132 + k];
        const float* wp = ws + k * 132 + tx * 8;
        float wv[8];
#pragma unroll
        for (int j = 0; j < 8; j++) wv[j] = wp[j];
#pragma unroll
        for (int i = 0; i < 4; i++)
#pragma unroll
            for (int j = 0; j < 8; j++) acc[i][j] = fmaf(xv[i], wv[j], acc[i][j]);
    }

    const int g  = tx >> 2;
    const int cb = g * 32 + (tx & 3) * 8;
    float As[8], Ad[8];
    {
        float4 a0 = __ldg((const float4*)(att_src + cb));
        float4 a1 = __ldg((const float4*)(att_src + cb + 4));
        float4 b0 = __ldg((const float4*)(att_dst + cb));
        float4 b1 = __ldg((const float4*)(att_dst + cb + 4));
        As[0]=a0.x;As[1]=a0.y;As[2]=a0.z;As[3]=a0.w;As[4]=a1.x;As[5]=a1.y;As[6]=a1.z;As[7]=a1.w;
        Ad[0]=b0.x;Ad[1]=b0.y;Ad[2]=b0.z;Ad[3]=b0.w;Ad[4]=b1.x;Ad[5]=b1.y;Ad[6]=b1.z;Ad[7]=b1.w;
    }
    float pa[4], pb[4];
#pragma unroll
    for (int i = 0; i < 4; i++) {
        float s = 0.f, d = 0.f;
#pragma unroll
        for (int j = 0; j < 8; j++) { s = fmaf(acc[i][j], As[j], s); d = fmaf(acc[i][j], Ad[j], d); }
        pa[i] = s; pb[i] = d;
    }
#pragma unroll
    for (int off = 1; off <= 2; off <<= 1) {
#pragma unroll
        for (int i = 0; i < 4; i++) {
            pa[i] += __shfl_xor_sync(0xffffffffu, pa[i], off);
            pb[i] += __shfl_xor_sync(0xffffffffu, pb[i], off);
        }
    }

#pragma unroll
    for (int i = 0; i < 4; i++) {
        int r = m0 + ty * 4 + i;
        if (r < N_NODES) {
            __half2 hp[4];
            hp[0] = __floats2half2_rn(acc[i][0], acc[i][1]);
            hp[1] = __floats2half2_rn(acc[i][2], acc[i][3]);
            hp[2] = __floats2half2_rn(acc[i][4], acc[i][5]);
            hp[3] = __floats2half2_rn(acc[i][6], acc[i][7]);
            *(uint4*)(g_hh + (size_t)r * 128 + tx * 8) = *(uint4*)hp;
            if ((tx & 3) == 0) {
                g_asrc[r * 4 + g] = pa[i];
                g_adst[r * 4 + g] = pb[i];
            }
        }
    }
}

// ---------------- CSR build ----------------
__global__ void k_zero_cnt() {
    int t = blockIdx.x * blockDim.x + threadIdx.x;
    if (t < N_NODES) g_cnt[t] = 0;
}

__global__ void k_count(const int* __restrict__ dst) {
    int t = blockIdx.x * blockDim.x + threadIdx.x;
    if (t >= N_EDGES / 4) return;
    int4 d = ((const int4*)dst)[t];
    atomicAdd(&g_cnt[d.x], 1);
    atomicAdd(&g_cnt[d.y], 1);
    atomicAdd(&g_cnt[d.z], 1);
    atomicAdd(&g_cnt[d.w], 1);
}

// ---- two-level parallel scan of (cnt[i] + 1) ----
__global__ __launch_bounds__(SB) void k_blocksum() {
    __shared__ int wsum[SB / 32];
    int t = blockIdx.x * SB + threadIdx.x;
    int v = (t < N_NODES) ? (g_cnt[t] + 1) : 0;
#pragma unroll
    for (int off = 16; off; off >>= 1) v += __shfl_xor_sync(0xffffffffu, v, off);
    if ((threadIdx.x & 31) == 0) wsum[threadIdx.x >> 5] = v;
    __syncthreads();
    if (threadIdx.x < SB / 32) {
        int s = wsum[threadIdx.x];
#pragma unroll
        for (int off = 16; off; off >>= 1) s += __shfl_xor_sync(0xffffffffu, s, off);
        if (threadIdx.x == 0) g_bsum[blockIdx.x] = s;
    }
}

__global__ void k_topscan() {
    // 64 threads; exclusive scan of NB (49) block sums
    int t = threadIdx.x;
    int v = (t < NB) ? g_bsum[t] : 0;
    int inc = v;
#pragma unroll
    for (int off = 1; off < 32; off <<= 1) {
        int o = __shfl_up_sync(0xffffffffu, inc, off);
        if ((t & 31) >= off) inc += o;
    }
    __shared__ int wtot[2];
    if ((t & 31) == 31) wtot[t >> 5] = inc;
    __syncthreads();
    int base = (t >= 32) ? wtot[0] : 0;
    if (t < NB) g_boff[t] = base + inc - v;   // exclusive
    if (t == 0) g_rowstart[N_NODES] = E_TOT;
}

__global__ __launch_bounds__(SB) void k_writeoff() {
    __shared__ int wsum[SB / 32];
    int t = blockIdx.x * SB + threadIdx.x;
    int lane = threadIdx.x & 31, w = threadIdx.x >> 5;
    int v = (t < N_NODES) ? (g_cnt[t] + 1) : 0;
    int inc = v;
#pragma unroll
    for (int off = 1; off < 32; off <<= 1) {
        int o = __shfl_up_sync(0xffffffffu, inc, off);
        if (lane >= off) inc += o;
    }
    if (lane == 31) wsum[w] = inc;
    __syncthreads();
    if (w == 0) {
        int s = (lane < SB / 32) ? wsum[lane] : 0;
        int si = s;
#pragma unroll
        for (int off = 1; off < 32; off <<= 1) {
            int o = __shfl_up_sync(0xffffffffu, si, off);
            if (lane >= off) si += o;
        }
        if (lane < SB / 32) wsum[lane] = si - s;   // exclusive warp offsets
    }
    __syncthreads();
    if (t < N_NODES) {
        int pos = g_boff[blockIdx.x] + wsum[w] + inc - v;
        g_rowstart[t] = pos;
        g_cur[t] = pos;
    }
}

__global__ void k_place(const int* __restrict__ src, const int* __restrict__ dst) {
    int e = blockIdx.x * blockDim.x + threadIdx.x;
    if (e >= E_TOT) return;
    int d, s;
    if (e < N_EDGES) { s = src[e]; d = dst[e]; }
    else             { s = e - N_EDGES; d = s; }
    int pos = atomicAdd(&g_cur[d], 1);
    g_sed[pos] = make_int2(s, e);
}

// ---------------- K3: softmax (no max-shift) + aggregate + alpha, one warp per node ----
__global__ __launch_bounds__(256) void k_agg(const float* __restrict__ bias,
                                             float* __restrict__ out,
                                             float* __restrict__ alpha_out) {
    int gt = blockIdx.x * blockDim.x + threadIdx.x;
    int warp = gt >> 5, lane = gt & 31;
    int nw = (gridDim.x * blockDim.x) >> 5;
    int hd = lane >> 3;

    float4 b = *(const float4*)(bias + lane * 4);

    for (int n = warp; n < N_NODES; n += nw) {
        int beg = g_rowstart[n];
        int end = g_rowstart[n + 1];
        float ad = g_adst[n * 4 + hd];

        float den = 0.f;
        float4 acc = make_float4(0.f, 0.f, 0.f, 0.f);
        for (int p = beg; p < end; p++) {
            int2 se = g_sed[p];
            float lg = g_asrc[se.x * 4 + hd] + ad;
            lg = lg > 0.f ? lg : NEG_SLOPE * lg;
            float ex = __expf(lg);
            den += ex;
            uint2 hv = *(const uint2*)(g_hh + (size_t)se.x * 128 + lane * 4);
            float2 f0 = __half22float2(*(__half2*)&hv.x);
            float2 f1 = __half22float2(*(__half2*)&hv.y);
            acc.x = fmaf(ex, f0.x, acc.x);
            acc.y = fmaf(ex, f0.y, acc.y);
            acc.z = fmaf(ex, f1.x, acc.z);
            acc.w = fmaf(ex, f1.y, acc.w);
            if (alpha_out && (lane & 7) == 0)
                alpha_out[(size_t)se.y * 4 + hd] = ex;
        }

        float inv = 1.f / (den + 1e-16f);
        float4 o;
        o.x = fmaf(acc.x, inv, b.x);
        o.y = fmaf(acc.y, inv, b.y);
        o.z = fmaf(acc.z, inv, b.z);
        o.w = fmaf(acc.w, inv, b.w);
        *(float4*)(out + (size_t)n * 128 + lane * 4) = o;

        if (alpha_out) {
            float i0 = __shfl_sync(0xffffffffu, inv, 0);
            float i1 = __shfl_sync(0xffffffffu, inv, 8);
            float i2 = __shfl_sync(0xffffffffu, inv, 16);
            float i3 = __shfl_sync(0xffffffffu, inv, 24);
            __syncwarp();
            for (int p = beg + lane; p < end; p += 32) {
                int e = g_sed[p].y;
                float4 v = *(float4*)(alpha_out + (size_t)e * 4);
                v.x *= i0; v.y *= i1; v.z *= i2; v.w *= i3;
                *(float4*)(alpha_out + (size_t)e * 4) = v;
            }
        }
    }
}

// ---------------- launch ----------------
extern "C" void kernel_launch(void* const* d_in, const int* in_sizes, int n_in,
                              void* d_out, int out_size) {
    const float* x       = (const float*)d_in[0];
    const int*   ei      = (const int*)d_in[1];   // [2, E] int32
    const float* W       = (const float*)d_in[2];
    const float* att_src = (const float*)d_in[3];
    const float* att_dst = (const float*)d_in[4];
    const float* bias    = (const float*)d_in[5];
    float* out = (float*)d_out;

    const int* src = ei;
    const int* dst = ei + N_EDGES;

    float* alpha_out = (out_size >= NHC + E_TOT * HEADS) ? (out + NHC) : nullptr;

    const int GEMM_SMEM = (128 + 64) * 132 * 4;  // 101376 bytes
    cudaFuncSetAttribute(k_gemm, cudaFuncAttributeMaxDynamicSharedMemorySize, GEMM_SMEM);

    k_gemm<<<(N_NODES + 63) / 64, 256, GEMM_SMEM>>>(x, W, att_src, att_dst);

    k_zero_cnt<<<(N_NODES + 255) / 256, 256>>>();
    k_count<<<(N_EDGES / 4 + 255) / 256, 256>>>(dst);
    k_blocksum<<<NB, SB>>>();
    k_topscan<<<1, 64>>>();
    k_writeoff<<<NB, SB>>>();
    k_place<<<(E_TOT + 255) / 256, 256>>>(src, dst);

    k_agg<<<6250, 256>>>(bias, out, alpha_out);
}

// round 4
// speedup vs baseline: 1.5252x; 1.0912x over previous
#include <cuda_runtime.h>
#include <cuda_fp16.h>
#include <math.h>
#include <float.h>
#include <stdint.h>

#define N_NODES 50000
#define N_EDGES 1600000
#define E_TOT   1650000      // edges + self loops
#define IN_CH   128
#define HC      128          // HEADS * OUT_CH
#define HEADS   4
#define NHC     (N_NODES * HC)   // 6,400,000
#define NEG_SLOPE 0.2f

#define SB 1024
#define NB ((N_NODES + SB - 1) / SB)   // 49 scan blocks

// ---------------- device scratch (static: no allocations allowed) ----------------
__device__ __align__(16) __half g_hh[(size_t)NHC];   // projected features fp16 [N,128]
__device__ __align__(16) float g_asrc[N_NODES * HEADS];
__device__ __align__(16) float g_adst[N_NODES * HEADS];
__device__ int   g_cnt[N_NODES];
__device__ int   g_cur[N_NODES];
__device__ int   g_rowstart[N_NODES + 1];
__device__ int   g_bsum[NB];
__device__ int   g_boff[NB];
__device__ __align__(16) int2   g_sed[E_TOT];        // {src, edge_id} grouped by dst
__device__ __align__(16) float4 g_ex[E_TOT];         // exp(leaky(logit)) per head, CSR order

// ---------------- K1: h = x @ W (fp32) + fused att dots, fp16 h output ----------------
__global__ __launch_bounds__(256) void k_gemm(const float* __restrict__ x,
                                              const float* __restrict__ W,
                                              const float* __restrict__ att_src,
                                              const float* __restrict__ att_dst) {
    extern __shared__ float sm[];
    float* ws = sm;                 // [128][132]
    float* xs = sm + 128 * 132;     // [64][132]

    const int tid = threadIdx.x;
    const int m0  = blockIdx.x * 64;

    const float4* W4 = (const float4*)W;
    for (int i = tid; i < 128 * 32; i += 256) {
        int k = i >> 5, c4 = i & 31;
        float4 w = W4[i];
        float* p = ws + k * 132 + c4 * 4;
        p[0] = w.x; p[1] = w.y; p[2] = w.z; p[3] = w.w;
    }
    const float4* x4 = (const float4*)x;
    for (int i = tid; i < 64 * 32; i += 256) {
        int r = i >> 5, c4 = i & 31;
        int gr = m0 + r;
        float4 v = make_float4(0.f, 0.f, 0.f, 0.f);
        if (gr < N_NODES) v = x4[(size_t)gr * 32 + c4];
        float* p = xs + r * 132 + c4 * 4;
        p[0] = v.x; p[1] = v.y; p[2] = v.z; p[3] = v.w;
    }
    __syncthreads();

    const int tx = tid & 15, ty = tid >> 4;
    float acc[4][8];
#pragma unroll
    for (int i = 0; i < 4; i++)
#pragma unroll
        for (int j = 0; j < 8; j++) acc[i][j] = 0.f;

#pragma unroll 4
    for (int k = 0; k < 128; k++) {
        float xv[4];
#pragma unroll
        for (int i = 0; i < 4; i++) xv[i] = xs[(ty * 4 + i) * 132 + k];
        const float* wp = ws + k * 132 + tx * 8;
        float wv[8];
#pragma unroll
        for (int j = 0; j < 8; j++) wv[j] = wp[j];
#pragma unroll
        for (int i = 0; i < 4; i++)
#pragma unroll
            for (int j = 0; j < 8; j++) acc[i][j] = fmaf(xv[i], wv[j], acc[i][j]);
    }

    const int g  = tx >> 2;
    const int cb = g * 32 + (tx & 3) * 8;
    float As[8], Ad[8];
    {
        float4 a0 = __ldg((const float4*)(att_src + cb));
        float4 a1 = __ldg((const float4*)(att_src + cb + 4));
        float4 b0 = __ldg((const float4*)(att_dst + cb));
        float4 b1 = __ldg((const float4*)(att_dst + cb + 4));
        As[0]=a0.x;As[1]=a0.y;As[2]=a0.z;As[3]=a0.w;As[4]=a1.x;As[5]=a1.y;As[6]=a1.z;As[7]=a1.w;
        Ad[0]=b0.x;Ad[1]=b0.y;Ad[2]=b0.z;Ad[3]=b0.w;Ad[4]=b1.x;Ad[5]=b1.y;Ad[6]=b1.z;Ad[7]=b1.w;
    }
    float pa[4], pb[4];
#pragma unroll
    for (int i = 0; i < 4; i++) {
        float s = 0.f, d = 0.f;
#pragma unroll
        for (int j = 0; j < 8; j++) { s = fmaf(acc[i][j], As[j], s); d = fmaf(acc[i][j], Ad[j], d); }
        pa[i] = s; pb[i] = d;
    }
#pragma unroll
    for (int off = 1; off <= 2; off <<= 1) {
#pragma unroll
        for (int i = 0; i < 4; i++) {
            pa[i] += __shfl_xor_sync(0xffffffffu, pa[i], off);
            pb[i] += __shfl_xor_sync(0xffffffffu, pb[i], off);
        }
    }

#pragma unroll
    for (int i = 0; i < 4; i++) {
        int r = m0 + ty * 4 + i;
        if (r < N_NODES) {
            __half2 hp[4];
            hp[0] = __floats2half2_rn(acc[i][0], acc[i][1]);
            hp[1] = __floats2half2_rn(acc[i][2], acc[i][3]);
            hp[2] = __floats2half2_rn(acc[i][4], acc[i][5]);
            hp[3] = __floats2half2_rn(acc[i][6], acc[i][7]);
            *(uint4*)(g_hh + (size_t)r * 128 + tx * 8) = *(uint4*)hp;
            if ((tx & 3) == 0) {
                g_asrc[r * 4 + g] = pa[i];
                g_adst[r * 4 + g] = pb[i];
            }
        }
    }
}

// ---------------- CSR build ----------------
__global__ void k_zero_cnt() {
    int t = blockIdx.x * blockDim.x + threadIdx.x;
    if (t < N_NODES) g_cnt[t] = 0;
}

__global__ void k_count(const int* __restrict__ dst) {
    int t = blockIdx.x * blockDim.x + threadIdx.x;
    if (t >= N_EDGES / 4) return;
    int4 d = ((const int4*)dst)[t];
    atomicAdd(&g_cnt[d.x], 1);
    atomicAdd(&g_cnt[d.y], 1);
    atomicAdd(&g_cnt[d.z], 1);
    atomicAdd(&g_cnt[d.w], 1);
}

// ---- two-level parallel scan of (cnt[i] + 1) ----
__global__ __launch_bounds__(SB) void k_blocksum() {
    __shared__ int wsum[SB / 32];
    int t = blockIdx.x * SB + threadIdx.x;
    int v = (t < N_NODES) ? (g_cnt[t] + 1) : 0;
#pragma unroll
    for (int off = 16; off; off >>= 1) v += __shfl_xor_sync(0xffffffffu, v, off);
    if ((threadIdx.x & 31) == 0) wsum[threadIdx.x >> 5] = v;
    __syncthreads();
    if (threadIdx.x < SB / 32) {
        int s = wsum[threadIdx.x];
#pragma unroll
        for (int off = 16; off; off >>= 1) s += __shfl_xor_sync(0xffffffffu, s, off);
        if (threadIdx.x == 0) g_bsum[blockIdx.x] = s;
    }
}

__global__ void k_topscan() {
    int t = threadIdx.x;
    int v = (t < NB) ? g_bsum[t] : 0;
    int inc = v;
#pragma unroll
    for (int off = 1; off < 32; off <<= 1) {
        int o = __shfl_up_sync(0xffffffffu, inc, off);
        if ((t & 31) >= off) inc += o;
    }
    __shared__ int wtot[2];
    if ((t & 31) == 31) wtot[t >> 5] = inc;
    __syncthreads();
    int base = (t >= 32) ? wtot[0] : 0;
    if (t < NB) g_boff[t] = base + inc - v;   // exclusive
    if (t == 0) g_rowstart[N_NODES] = E_TOT;
}

__global__ __launch_bounds__(SB) void k_writeoff() {
    __shared__ int wsum[SB / 32];
    int t = blockIdx.x * SB + threadIdx.x;
    int lane = threadIdx.x & 31, w = threadIdx.x >> 5;
    int v = (t < N_NODES) ? (g_cnt[t] + 1) : 0;
    int inc = v;
#pragma unroll
    for (int off = 1; off < 32; off <<= 1) {
        int o = __shfl_up_sync(0xffffffffu, inc, off);
        if (lane >= off) inc += o;
    }
    if (lane == 31) wsum[w] = inc;
    __syncthreads();
    if (w == 0) {
        int s = (lane < SB / 32) ? wsum[lane] : 0;
        int si = s;
#pragma unroll
        for (int off = 1; off < 32; off <<= 1) {
            int o = __shfl_up_sync(0xffffffffu, si, off);
            if (lane >= off) si += o;
        }
        if (lane < SB / 32) wsum[lane] = si - s;
    }
    __syncthreads();
    if (t < N_NODES) {
        int pos = g_boff[blockIdx.x] + wsum[w] + inc - v;
        g_rowstart[t] = pos;
        g_cur[t] = pos;
    }
}

// ---- placement + fused per-edge attention exp (all 4 heads) ----
__device__ __forceinline__ float lrelu_exp(float a, float b) {
    float lg = a + b;
    lg = lg > 0.f ? lg : NEG_SLOPE * lg;
    return __expf(lg);     // logits bounded ~|10|: safe shift-free softmax
}

__global__ void k_place(const int* __restrict__ src, const int* __restrict__ dst) {
    int e = blockIdx.x * blockDim.x + threadIdx.x;
    if (e >= E_TOT) return;
    int d, s;
    if (e < N_EDGES) { s = src[e]; d = dst[e]; }
    else             { s = e - N_EDGES; d = s; }
    float4 as = *(const float4*)(g_asrc + (size_t)s * 4);
    float4 ad = *(const float4*)(g_adst + (size_t)d * 4);
    float4 ex;
    ex.x = lrelu_exp(as.x, ad.x);
    ex.y = lrelu_exp(as.y, ad.y);
    ex.z = lrelu_exp(as.z, ad.z);
    ex.w = lrelu_exp(as.w, ad.w);
    int pos = atomicAdd(&g_cur[d], 1);
    g_sed[pos] = make_int2(s, e);
    g_ex[pos]  = ex;
}

// ---------------- K3: aggregate + alpha, one warp per node ----------------
__global__ __launch_bounds__(256) void k_agg(const float* __restrict__ bias,
                                             float* __restrict__ out,
                                             float* __restrict__ alpha_out) {
    int gt = blockIdx.x * blockDim.x + threadIdx.x;
    int warp = gt >> 5, lane = gt & 31;
    int nw = (gridDim.x * blockDim.x) >> 5;
    int hd = lane >> 3;

    const float* exs = (const float*)g_ex;
    float4 b = *(const float4*)(bias + lane * 4);

    for (int n = warp; n < N_NODES; n += nw) {
        int beg = g_rowstart[n];
        int end = g_rowstart[n + 1];

        float den = 0.f;
        float4 acc = make_float4(0.f, 0.f, 0.f, 0.f);
#pragma unroll 4
        for (int p = beg; p < end; p++) {
            int s = g_sed[p].x;
            float ex = exs[(size_t)p * 4 + hd];   // one 16B line, warp-broadcast
            den += ex;
            uint2 hv = *(const uint2*)(g_hh + (size_t)s * 128 + lane * 4);
            float2 f0 = __half22float2(*(__half2*)&hv.x);
            float2 f1 = __half22float2(*(__half2*)&hv.y);
            acc.x = fmaf(ex, f0.x, acc.x);
            acc.y = fmaf(ex, f0.y, acc.y);
            acc.z = fmaf(ex, f1.x, acc.z);
            acc.w = fmaf(ex, f1.y, acc.w);
        }

        float inv = 1.f / (den + 1e-16f);
        float4 o;
        o.x = fmaf(acc.x, inv, b.x);
        o.y = fmaf(acc.y, inv, b.y);
        o.z = fmaf(acc.z, inv, b.z);
        o.w = fmaf(acc.w, inv, b.w);
        *(float4*)(out + (size_t)n * 128 + lane * 4) = o;

        if (alpha_out) {
            float i0 = __shfl_sync(0xffffffffu, inv, 0);
            float i1 = __shfl_sync(0xffffffffu, inv, 8);
            float i2 = __shfl_sync(0xffffffffu, inv, 16);
            float i3 = __shfl_sync(0xffffffffu, inv, 24);
            for (int p = beg + lane; p < end; p += 32) {
                float4 v = g_ex[p];
                int e = g_sed[p].y;
                v.x *= i0; v.y *= i1; v.z *= i2; v.w *= i3;
                *(float4*)(alpha_out + (size_t)e * 4) = v;   // write-once
            }
        }
    }
}

// ---------------- launch ----------------
extern "C" void kernel_launch(void* const* d_in, const int* in_sizes, int n_in,
                              void* d_out, int out_size) {
    const float* x       = (const float*)d_in[0];
    const int*   ei      = (const int*)d_in[1];   // [2, E] int32
    const float* W       = (const float*)d_in[2];
    const float* att_src = (const float*)d_in[3];
    const float* att_dst = (const float*)d_in[4];
    const float* bias    = (const float*)d_in[5];
    float* out = (float*)d_out;

    const int* src = ei;
    const int* dst = ei + N_EDGES;

    float* alpha_out = (out_size >= NHC + E_TOT * HEADS) ? (out + NHC) : nullptr;

    const int GEMM_SMEM = (128 + 64) * 132 * 4;  // 101376 bytes
    cudaFuncSetAttribute(k_gemm, cudaFuncAttributeMaxDynamicSharedMemorySize, GEMM_SMEM);

    k_gemm<<<(N_NODES + 63) / 64, 256, GEMM_SMEM>>>(x, W, att_src, att_dst);

    k_zero_cnt<<<(N_NODES + 255) / 256, 256>>>();
    k_count<<<(N_EDGES / 4 + 255) / 256, 256>>>(dst);
    k_blocksum<<<NB, SB>>>();
    k_topscan<<<1, 64>>>();
    k_writeoff<<<NB, SB>>>();
    k_place<<<(E_TOT + 255) / 256, 256>>>(src, dst);

    k_agg<<<6250, 256>>>(bias, out, alpha_out);
}

// round 5
// speedup vs baseline: 1.5928x; 1.0443x over previous
#include <cuda_runtime.h>
#include <cuda_fp16.h>
#include <math.h>
#include <float.h>
#include <stdint.h>

#define N_NODES 50000
#define N_EDGES 1600000
#define E_TOT   1650000      // edges + self loops
#define IN_CH   128
#define HC      128          // HEADS * OUT_CH
#define HEADS   4
#define NHC     (N_NODES * HC)   // 6,400,000
#define NEG_SLOPE 0.2f

#define SB 1024
#define NB ((N_NODES + SB - 1) / SB)   // 49 scan blocks

// ---------------- device scratch (static: no allocations allowed) ----------------
__device__ __align__(16) __half g_hh[(size_t)NHC];   // projected features fp16 [N,128]
__device__ __align__(16) float g_asrc[N_NODES * HEADS];
__device__ __align__(16) float g_adst[N_NODES * HEADS];
__device__ int   g_cnt[N_NODES];
__device__ int   g_cur[N_NODES];
__device__ int   g_rowstart[N_NODES + 1];
__device__ int   g_bsum[NB];
__device__ int   g_boff[NB];
__device__ __align__(16) int2   g_sed[E_TOT];        // {src, edge_id} grouped by dst
__device__ __align__(16) float4 g_ex[E_TOT];         // exp(leaky(logit)) per head, CSR order

// ---------------- K1: h = x @ W (fp32) + fused att dots, fp16 h output ----------------
__global__ __launch_bounds__(256) void k_gemm(const float* __restrict__ x,
                                              const float* __restrict__ W,
                                              const float* __restrict__ att_src,
                                              const float* __restrict__ att_dst) {
    extern __shared__ float sm[];
    float* ws = sm;                 // [128][132]
    float* xs = sm + 128 * 132;     // [64][132]

    const int tid = threadIdx.x;
    const int m0  = blockIdx.x * 64;

    const float4* W4 = (const float4*)W;
    for (int i = tid; i < 128 * 32; i += 256) {
        int k = i >> 5, c4 = i & 31;
        float4 w = W4[i];
        float* p = ws + k * 132 + c4 * 4;
        p[0] = w.x; p[1] = w.y; p[2] = w.z; p[3] = w.w;
    }
    const float4* x4 = (const float4*)x;
    for (int i = tid; i < 64 * 32; i += 256) {
        int r = i >> 5, c4 = i & 31;
        int gr = m0 + r;
        float4 v = make_float4(0.f, 0.f, 0.f, 0.f);
        if (gr < N_NODES) v = x4[(size_t)gr * 32 + c4];
        float* p = xs + r * 132 + c4 * 4;
        p[0] = v.x; p[1] = v.y; p[2] = v.z; p[3] = v.w;
    }
    __syncthreads();

    const int tx = tid & 15, ty = tid >> 4;
    float acc[4][8];
#pragma unroll
    for (int i = 0; i < 4; i++)
#pragma unroll
        for (int j = 0; j < 8; j++) acc[i][j] = 0.f;

#pragma unroll 4
    for (int k = 0; k < 128; k++) {
        float xv[4];
#pragma unroll
        for (int i = 0; i < 4; i++) xv[i] = xs[(ty * 4 + i) * 132 + k];
        const float* wp = ws + k * 132 + tx * 8;
        float wv[8];
#pragma unroll
        for (int j = 0; j < 8; j++) wv[j] = wp[j];
#pragma unroll
        for (int i = 0; i < 4; i++)
#pragma unroll
            for (int j = 0; j < 8; j++) acc[i][j] = fmaf(xv[i], wv[j], acc[i][j]);
    }

    const int g  = tx >> 2;
    const int cb = g * 32 + (tx & 3) * 8;
    float As[8], Ad[8];
    {
        float4 a0 = __ldg((const float4*)(att_src + cb));
        float4 a1 = __ldg((const float4*)(att_src + cb + 4));
        float4 b0 = __ldg((const float4*)(att_dst + cb));
        float4 b1 = __ldg((const float4*)(att_dst + cb + 4));
        As[0]=a0.x;As[1]=a0.y;As[2]=a0.z;As[3]=a0.w;As[4]=a1.x;As[5]=a1.y;As[6]=a1.z;As[7]=a1.w;
        Ad[0]=b0.x;Ad[1]=b0.y;Ad[2]=b0.z;Ad[3]=b0.w;Ad[4]=b1.x;Ad[5]=b1.y;Ad[6]=b1.z;Ad[7]=b1.w;
    }
    float pa[4], pb[4];
#pragma unroll
    for (int i = 0; i < 4; i++) {
        float s = 0.f, d = 0.f;
#pragma unroll
        for (int j = 0; j < 8; j++) { s = fmaf(acc[i][j], As[j], s); d = fmaf(acc[i][j], Ad[j], d); }
        pa[i] = s; pb[i] = d;
    }
#pragma unroll
    for (int off = 1; off <= 2; off <<= 1) {
#pragma unroll
        for (int i = 0; i < 4; i++) {
            pa[i] += __shfl_xor_sync(0xffffffffu, pa[i], off);
            pb[i] += __shfl_xor_sync(0xffffffffu, pb[i], off);
        }
    }

#pragma unroll
    for (int i = 0; i < 4; i++) {
        int r = m0 + ty * 4 + i;
        if (r < N_NODES) {
            __half2 hp[4];
            hp[0] = __floats2half2_rn(acc[i][0], acc[i][1]);
            hp[1] = __floats2half2_rn(acc[i][2], acc[i][3]);
            hp[2] = __floats2half2_rn(acc[i][4], acc[i][5]);
            hp[3] = __floats2half2_rn(acc[i][6], acc[i][7]);
            *(uint4*)(g_hh + (size_t)r * 128 + tx * 8) = *(uint4*)hp;
            if ((tx & 3) == 0) {
                g_asrc[r * 4 + g] = pa[i];
                g_adst[r * 4 + g] = pb[i];
            }
        }
    }
}

// ---------------- CSR build ----------------
__global__ void k_zero_cnt() {
    int t = blockIdx.x * blockDim.x + threadIdx.x;
    if (t < N_NODES) g_cnt[t] = 0;
}

__global__ void k_count(const int* __restrict__ dst) {
    int t = blockIdx.x * blockDim.x + threadIdx.x;
    if (t >= N_EDGES / 4) return;
    int4 d = ((const int4*)dst)[t];
    atomicAdd(&g_cnt[d.x], 1);
    atomicAdd(&g_cnt[d.y], 1);
    atomicAdd(&g_cnt[d.z], 1);
    atomicAdd(&g_cnt[d.w], 1);
}

// ---- two-level parallel scan of (cnt[i] + 1) ----
__global__ __launch_bounds__(SB) void k_blocksum() {
    __shared__ int wsum[SB / 32];
    int t = blockIdx.x * SB + threadIdx.x;
    int v = (t < N_NODES) ? (g_cnt[t] + 1) : 0;
#pragma unroll
    for (int off = 16; off; off >>= 1) v += __shfl_xor_sync(0xffffffffu, v, off);
    if ((threadIdx.x & 31) == 0) wsum[threadIdx.x >> 5] = v;
    __syncthreads();
    if (threadIdx.x < SB / 32) {
        int s = wsum[threadIdx.x];
#pragma unroll
        for (int off = 16; off; off >>= 1) s += __shfl_xor_sync(0xffffffffu, s, off);
        if (threadIdx.x == 0) g_bsum[blockIdx.x] = s;
    }
}

__global__ void k_topscan() {
    int t = threadIdx.x;
    int v = (t < NB) ? g_bsum[t] : 0;
    int inc = v;
#pragma unroll
    for (int off = 1; off < 32; off <<= 1) {
        int o = __shfl_up_sync(0xffffffffu, inc, off);
        if ((t & 31) >= off) inc += o;
    }
    __shared__ int wtot[2];
    if ((t & 31) == 31) wtot[t >> 5] = inc;
    __syncthreads();
    int base = (t >= 32) ? wtot[0] : 0;
    if (t < NB) g_boff[t] = base + inc - v;   // exclusive
    if (t == 0) g_rowstart[N_NODES] = E_TOT;
}

__global__ __launch_bounds__(SB) void k_writeoff() {
    __shared__ int wsum[SB / 32];
    int t = blockIdx.x * SB + threadIdx.x;
    int lane = threadIdx.x & 31, w = threadIdx.x >> 5;
    int v = (t < N_NODES) ? (g_cnt[t] + 1) : 0;
    int inc = v;
#pragma unroll
    for (int off = 1; off < 32; off <<= 1) {
        int o = __shfl_up_sync(0xffffffffu, inc, off);
        if (lane >= off) inc += o;
    }
    if (lane == 31) wsum[w] = inc;
    __syncthreads();
    if (w == 0) {
        int s = (lane < SB / 32) ? wsum[lane] : 0;
        int si = s;
#pragma unroll
        for (int off = 1; off < 32; off <<= 1) {
            int o = __shfl_up_sync(0xffffffffu, si, off);
            if (lane >= off) si += o;
        }
        if (lane < SB / 32) wsum[lane] = si - s;
    }
    __syncthreads();
    if (t < N_NODES) {
        int pos = g_boff[blockIdx.x] + wsum[w] + inc - v;
        g_rowstart[t] = pos;
        g_cur[t] = pos;
    }
}

// ---- placement + fused per-edge attention exp (all 4 heads) ----
__device__ __forceinline__ float lrelu_exp(float a, float b) {
    float lg = a + b;
    lg = lg > 0.f ? lg : NEG_SLOPE * lg;
    return __expf(lg);     // logits bounded ~|10|: safe shift-free softmax
}

__global__ void k_place(const int* __restrict__ src, const int* __restrict__ dst) {
    int e = blockIdx.x * blockDim.x + threadIdx.x;
    if (e >= E_TOT) return;
    int d, s;
    if (e < N_EDGES) { s = src[e]; d = dst[e]; }
    else             { s = e - N_EDGES; d = s; }
    float4 as = __ldg((const float4*)(g_asrc + (size_t)s * 4));
    float4 ad = __ldg((const float4*)(g_adst + (size_t)d * 4));
    float4 ex;
    ex.x = lrelu_exp(as.x, ad.x);
    ex.y = lrelu_exp(as.y, ad.y);
    ex.z = lrelu_exp(as.z, ad.z);
    ex.w = lrelu_exp(as.w, ad.w);
    int pos = atomicAdd(&g_cur[d], 1);
    g_sed[pos] = make_int2(s, e);
    g_ex[pos]  = ex;
}

// ---------------- K3: aggregate + alpha, one warp per node ----------------
__global__ __launch_bounds__(256) void k_agg(const float* __restrict__ bias,
                                             float* __restrict__ out,
                                             float* __restrict__ alpha_out) {
    int gt = blockIdx.x * blockDim.x + threadIdx.x;
    int warp = gt >> 5, lane = gt & 31;
    int nw = (gridDim.x * blockDim.x) >> 5;
    int hd = lane >> 3;

    const float* exs = (const float*)g_ex;
    float4 b = *(const float4*)(bias + lane * 4);

    for (int n = warp; n < N_NODES; n += nw) {
        int beg = g_rowstart[n];
        int end = g_rowstart[n + 1];

        float den = 0.f;
        float4 acc = make_float4(0.f, 0.f, 0.f, 0.f);
#pragma unroll 4
        for (int p = beg; p < end; p++) {
            int s = g_sed[p].x;
            float ex = exs[(size_t)p * 4 + hd];   // one 16B line, warp-broadcast
            den += ex;
            uint2 hv = *(const uint2*)(g_hh + (size_t)s * 128 + lane * 4);
            float2 f0 = __half22float2(*(__half2*)&hv.x);
            float2 f1 = __half22float2(*(__half2*)&hv.y);
            acc.x = fmaf(ex, f0.x, acc.x);
            acc.y = fmaf(ex, f0.y, acc.y);
            acc.z = fmaf(ex, f1.x, acc.z);
            acc.w = fmaf(ex, f1.y, acc.w);
        }

        float inv = 1.f / (den + 1e-16f);
        float4 o;
        o.x = fmaf(acc.x, inv, b.x);
        o.y = fmaf(acc.y, inv, b.y);
        o.z = fmaf(acc.z, inv, b.z);
        o.w = fmaf(acc.w, inv, b.w);
        *(float4*)(out + (size_t)n * 128 + lane * 4) = o;

        if (alpha_out) {
            float i0 = __shfl_sync(0xffffffffu, inv, 0);
            float i1 = __shfl_sync(0xffffffffu, inv, 8);
            float i2 = __shfl_sync(0xffffffffu, inv, 16);
            float i3 = __shfl_sync(0xffffffffu, inv, 24);
            for (int p = beg + lane; p < end; p += 32) {
                float4 v = g_ex[p];
                int e = g_sed[p].y;
                v.x *= i0; v.y *= i1; v.z *= i2; v.w *= i3;
                *(float4*)(alpha_out + (size_t)e * 4) = v;   // write-once
            }
        }
    }
}

// ---------------- launch ----------------
extern "C" void kernel_launch(void* const* d_in, const int* in_sizes, int n_in,
                              void* d_out, int out_size) {
    const float* x       = (const float*)d_in[0];
    const int*   ei      = (const int*)d_in[1];   // [2, E] int32
    const float* W       = (const float*)d_in[2];
    const float* att_src = (const float*)d_in[3];
    const float* att_dst = (const float*)d_in[4];
    const float* bias    = (const float*)d_in[5];
    float* out = (float*)d_out;

    const int* src = ei;
    const int* dst = ei + N_EDGES;

    float* alpha_out = (out_size >= NHC + E_TOT * HEADS) ? (out + NHC) : nullptr;

    // one-time host-side resources (no device memory)
    static cudaStream_t s_side = nullptr;
    static cudaEvent_t ev_fork = nullptr, ev_join = nullptr;
    static bool attr_set = false;
    const int GEMM_SMEM = (128 + 64) * 132 * 4;  // 101376 bytes
    if (!s_side) {
        cudaStreamCreateWithFlags(&s_side, cudaStreamNonBlocking);
        cudaEventCreateWithFlags(&ev_fork, cudaEventDisableTiming);
        cudaEventCreateWithFlags(&ev_join, cudaEventDisableTiming);
    }
    if (!attr_set) {
        cudaFuncSetAttribute(k_gemm, cudaFuncAttributeMaxDynamicSharedMemorySize, GEMM_SMEM);
        attr_set = true;
    }

    // fork: CSR-prefix chain on side stream, GEMM on main stream (independent DAGs)
    cudaEventRecord(ev_fork, 0);
    cudaStreamWaitEvent(s_side, ev_fork, 0);

    k_zero_cnt<<<(N_NODES + 255) / 256, 256, 0, s_side>>>();
    k_count<<<(N_EDGES / 4 + 255) / 256, 256, 0, s_side>>>(dst);
    k_blocksum<<<NB, SB, 0, s_side>>>();
    k_topscan<<<1, 64, 0, s_side>>>();
    k_writeoff<<<NB, SB, 0, s_side>>>();
    cudaEventRecord(ev_join, s_side);

    k_gemm<<<(N_NODES + 63) / 64, 256, GEMM_SMEM>>>(x, W, att_src, att_dst);

    // join: k_place needs both g_asrc/g_adst (gemm) and g_cur (writeoff)
    cudaStreamWaitEvent(0, ev_join, 0);

    k_place<<<(E_TOT + 255) / 256, 256>>>(src, dst);
    k_agg<<<6250, 256>>>(bias, out, alpha_out);
}